// round 5
// baseline (speedup 1.0000x reference)
#include <cuda_runtime.h>

#define HWPX (1024*1024)
#define NB 8
#define NA 8
#define NK 16
#define NSEG 17
#define EPSV 1e-4f

// per-batch constant block v3 (floats):
// [0,32)    : per-axis scalars, axis a at [a*4]: {A0*dxi, A1*dxi, A2*dxi, m2}
// [32,56)   : pinv rows, [a][3]
// [56,328)  : tab[a][k] as float2 (dy, c02), 8*17*2 = 272 floats
#define CB_AP   0
#define CB_PV   32
#define CB_TAB  56
#define CB_SIZE (56 + NA*NSEG*2)   // 328 floats

__device__ float g_consts[NB * CB_SIZE];

__global__ void precompute_kernel(const float* __restrict__ ys,
                                  const float* __restrict__ A) {
    int b = blockIdx.x;
    int t = threadIdx.x;
    const float* Ab = A + b * 3 * NA;
    float* cb = g_consts + b * CB_SIZE;

    if (t < NA) {
        int a = t;
        float Am[3][NA];
        #pragma unroll
        for (int c = 0; c < 3; c++)
            #pragma unroll
            for (int j = 0; j < NA; j++)
                Am[c][j] = Ab[c * NA + j];

        // M = A * A^T  (3x3)
        float M[3][3];
        #pragma unroll
        for (int i = 0; i < 3; i++)
            #pragma unroll
            for (int j = 0; j < 3; j++) {
                float s = 0.f;
                #pragma unroll
                for (int k = 0; k < NA; k++) s += Am[i][k] * Am[j][k];
                M[i][j] = s;
            }

        // analytic 3x3 inverse
        float c00 = M[1][1]*M[2][2] - M[1][2]*M[2][1];
        float c01 = M[1][2]*M[2][0] - M[1][0]*M[2][2];
        float c02 = M[1][0]*M[2][1] - M[1][1]*M[2][0];
        float det = M[0][0]*c00 + M[0][1]*c01 + M[0][2]*c02;
        float id  = 1.0f / det;
        float inv[3][3];
        inv[0][0] = c00 * id;
        inv[1][0] = c01 * id;
        inv[2][0] = c02 * id;
        inv[0][1] = (M[0][2]*M[2][1] - M[0][1]*M[2][2]) * id;
        inv[1][1] = (M[0][0]*M[2][2] - M[0][2]*M[2][0]) * id;
        inv[2][1] = (M[0][1]*M[2][0] - M[0][0]*M[2][1]) * id;
        inv[0][2] = (M[0][1]*M[1][2] - M[0][2]*M[1][1]) * id;
        inv[1][2] = (M[0][2]*M[1][0] - M[0][0]*M[1][2]) * id;
        inv[2][2] = (M[0][0]*M[1][1] - M[0][1]*M[1][0]) * id;

        // pinv[a][c] = sum_k A[k][a] * inv[k][c]
        #pragma unroll
        for (int c = 0; c < 3; c++) {
            float s = 0.f;
            #pragma unroll
            for (int k = 0; k < 3; k++) s += Am[k][a] * inv[k][c];
            cb[CB_PV + a * 3 + c] = s;
        }

        float mn = 0.f, mx = 0.f;
        #pragma unroll
        for (int c = 0; c < 3; c++) {
            float v = Am[c][a];
            mn += fminf(v, 0.f);
            mx += fmaxf(v, 0.f);
        }
        float dx  = (mx + EPSV - mn) / 17.0f;
        float dxi = 1.0f / dx;

        // scaled projection coefficients: u = r*A0' + g*A1' + b*A2' + m2
        cb[CB_AP + a * 4 + 0] = Am[0][a] * dxi;
        cb[CB_AP + a * 4 + 1] = Am[1][a] * dxi;
        cb[CB_AP + a * 4 + 2] = Am[2][a] * dxi;
        cb[CB_AP + a * 4 + 3] = -mn * dxi;

        // ys_full = [mins, ys[0..15], maxs]
        float ysf[18];
        ysf[0]  = mn;
        ysf[17] = mx;
        #pragma unroll
        for (int k = 0; k < NK; k++)
            ysf[k + 1] = ys[(b * NA + a) * NK + k];

        // est = ys_hi + (u - (k+1))*dy = fma(u, dy, c02)
        // dy_k = ysf[k+1]-ysf[k];  c02_k = ysf[k+1] - (k+1)*dy_k
        #pragma unroll
        for (int k = 0; k < NSEG; k++) {
            float dy   = ysf[k + 1] - ysf[k];
            float c02v = ysf[k + 1] - (float)(k + 1) * dy;
            cb[CB_TAB + (a * NSEG + k) * 2 + 0] = dy;
            cb[CB_TAB + (a * NSEG + k) * 2 + 1] = c02v;
        }
    }
}

__global__ __launch_bounds__(256, 8)
void spline_main_kernel(const float* __restrict__ raw, float* __restrict__ out) {
    __shared__ __align__(16) float sc[CB_SIZE];
    const int b = blockIdx.y;
    {
        const float* cb = g_consts + b * CB_SIZE;
        for (int i = threadIdx.x; i < CB_SIZE; i += 256) sc[i] = cb[i];
    }
    __syncthreads();

    const float*  sap  = sc + CB_AP;
    const float*  spv  = sc + CB_PV;
    const float2* stab = (const float2*)(sc + CB_TAB);

    const size_t base = (size_t)b * 3 * HWPX;
    const int vidx = blockIdx.x * 256 + threadIdx.x;   // float2 index within plane

    float2 R  = ((const float2*)(raw + base          ))[vidx];
    float2 G  = ((const float2*)(raw + base +   HWPX ))[vidx];
    float2 Bv = ((const float2*)(raw + base + 2*HWPX ))[vidx];

    float rr[2] = {R.x,  R.y};
    float gg[2] = {G.x,  G.y};
    float bb[2] = {Bv.x, Bv.y};

    float a0[2], a1[2], a2[2];
    #pragma unroll
    for (int q = 0; q < 2; q++) { a0[q] = 0.f; a1[q] = 0.f; a2[q] = 0.f; }

    #pragma unroll
    for (int a = 0; a < NA; a++) {
        const float A0  = sap[a * 4 + 0];
        const float A1  = sap[a * 4 + 1];
        const float A2  = sap[a * 4 + 2];
        const float M2  = sap[a * 4 + 3];
        const float pv0 = spv[a * 3 + 0];
        const float pv1 = spv[a * 3 + 1];
        const float pv2 = spv[a * 3 + 2];
        const float2* atab = stab + a * NSEG;
        #pragma unroll
        for (int q = 0; q < 2; q++) {
            // u in [0,17) by construction (EPS margin >> roundoff); trunc handles -eps
            float u = fmaf(rr[q], A0, fmaf(gg[q], A1, fmaf(bb[q], A2, M2)));
            int   k = (int)u;
            float2 tc = atab[k];
            float est = fmaf(u, tc.x, tc.y);
            a0[q] = fmaf(est, pv0, a0[q]);
            a1[q] = fmaf(est, pv1, a1[q]);
            a2[q] = fmaf(est, pv2, a2[q]);
        }
    }

    ((float2*)(out + base          ))[vidx] = make_float2(a0[0], a0[1]);
    ((float2*)(out + base +   HWPX ))[vidx] = make_float2(a1[0], a1[1]);
    ((float2*)(out + base + 2*HWPX ))[vidx] = make_float2(a2[0], a2[1]);
}

extern "C" void kernel_launch(void* const* d_in, const int* in_sizes, int n_in,
                              void* d_out, int out_size) {
    const float* raw = (const float*)d_in[0];
    const float* ys  = (const float*)d_in[1];
    const float* A   = (const float*)d_in[2];
    float* out = (float*)d_out;

    precompute_kernel<<<NB, 32>>>(ys, A);

    dim3 grid(HWPX / (256 * 2), NB);
    spline_main_kernel<<<grid, 256>>>(raw, out);
}